// round 14
// baseline (speedup 1.0000x reference)
#include <cuda_runtime.h>
#include <cuda_fp16.h>
#include <cstdint>

#define NN 2048
#define HH 256
#define NJ 5
#define RSQ2 0.70710678118654752440f

#define NA ((size_t)NN * NN)
#define NX ((size_t)NN * HH)
#define NW ((size_t)HH * HH)

// fp16 operands stored as ushort
__device__ unsigned short g_Af[NJ * NA];      // 41.9 MB  [j][node][k]
__device__ unsigned short g_Xf[NJ * NX];      //  5.2 MB  [j][hidden][node]
__device__ unsigned short g_Wf[NJ * NW];      //  0.65 MB [j][h_out][h_in]
__device__ unsigned short g_C1[NJ * NX];      //  5.2 MB  [j][node][h]
__device__ float          g_P1[4 * NJ * NX];  // 42 MB: GEMM1 4 K-piece slabs
__device__ float          g_P2[2 * NJ * NX];  // 21 MB: GEMM2 split-K2 partials

__device__ __forceinline__ uint32_t smem_u32(const void* p) {
    uint32_t a;
    asm("{ .reg .u64 t; cvta.to.shared.u64 t, %1; cvt.u32.u64 %0, t; }"
        : "=r"(a) : "l"(p));
    return a;
}
__device__ __forceinline__ void cp16(uint32_t dst, const void* src) {
    asm volatile("cp.async.cg.shared.global [%0], [%1], 16;" :: "r"(dst), "l"(src));
}
__device__ __forceinline__ void ldsm4(uint32_t& r0, uint32_t& r1, uint32_t& r2,
                                      uint32_t& r3, uint32_t addr) {
    asm volatile("ldmatrix.sync.aligned.m8n8.x4.shared.b16 {%0,%1,%2,%3}, [%4];"
                 : "=r"(r0), "=r"(r1), "=r"(r2), "=r"(r3) : "r"(addr));
}
__device__ __forceinline__ void mma16816(float* d, const uint32_t* a,
                                         uint32_t b0, uint32_t b1) {
    asm volatile(
        "mma.sync.aligned.m16n8k16.row.col.f32.f16.f16.f32 "
        "{%0,%1,%2,%3}, {%4,%5,%6,%7}, {%8,%9}, {%0,%1,%2,%3};"
        : "+f"(d[0]), "+f"(d[1]), "+f"(d[2]), "+f"(d[3])
        : "r"(a[0]), "r"(a[1]), "r"(a[2]), "r"(a[3]), "r"(b0), "r"(b1));
}

__device__ __forceinline__ void cos5(float4 lo, float4 hi, float f[5]) {
    float s04 = lo.x + hi.x, d04 = lo.x - hi.x;
    float s26 = lo.z + hi.z;
    float s15 = lo.y + hi.y, d15 = lo.y - hi.y;
    float s37 = lo.w + hi.w, d37 = lo.w - hi.w;
    float t = RSQ2 * (d15 - d37);
    f[0] = (s04 + s26) + (s15 + s37);
    f[1] = d04 + t;
    f[2] = s04 - s26;
    f[3] = d04 - t;
    f[4] = (s04 + s26) - (s15 + s37);
}
__device__ __forceinline__ unsigned short h16(float f) {
    __half h = __float2half_rn(f);
    return *reinterpret_cast<unsigned short*>(&h);
}

// Transform one 512-column K-piece of A: rows 0..2047, cols [kLo, kLo+512).
// One CTA = 256 threads x 8 elems = 2048 elements; 512 CTAs per piece.
__device__ __forceinline__ void transform_piece(const float* __restrict__ in,
                                                unsigned short* __restrict__ o,
                                                int kLo, int tIdx, int tid) {
    int tt = tIdx * 256 + tid;
    int row = tt >> 6;                   // 512/8 = 64 thread-chunks per row
    int col = kLo + ((tt & 63) << 3);
    size_t i0 = (size_t)row * NN + col;
    const float4* p = reinterpret_cast<const float4*>(in) + 2 * i0;
    unsigned short h[8][5];
#pragma unroll
    for (int e = 0; e < 8; e++) {
        float f[5]; cos5(p[2 * e], p[2 * e + 1], f);
#pragma unroll
        for (int j = 0; j < 5; j++) h[e][j] = h16(f[j]);
    }
#pragma unroll
    for (int j = 0; j < 5; j++) {
        *reinterpret_cast<uint4*>(o + j * NA + i0) =
            make_uint4((uint32_t)h[0][j] | ((uint32_t)h[1][j] << 16),
                       (uint32_t)h[2][j] | ((uint32_t)h[3][j] << 16),
                       (uint32_t)h[4][j] | ((uint32_t)h[5][j] << 16),
                       (uint32_t)h[6][j] | ((uint32_t)h[7][j] << 16));
    }
}

// standalone transform for piece 0 (prelude)
__global__ void fwd_A0_kernel(const float* __restrict__ in,
                              unsigned short* __restrict__ o) {
    transform_piece(in, o, 0, blockIdx.x, threadIdx.x);
}

// src [R][C][8] -> out [j][C][R] fp16 (transpose + cos)
__global__ void fwd_T_kernel(const float* __restrict__ in,
                             unsigned short* __restrict__ o,
                             int R, int C) {
    int i = blockIdx.x * blockDim.x + threadIdx.x;
    size_t n = (size_t)R * C;
    if (i >= (int)n) return;
    int c = i / R, r = i - c * R;
    const float4* p = reinterpret_cast<const float4*>(in) + 2 * ((size_t)r * C + c);
    float f[5]; cos5(p[0], p[1], f);
#pragma unroll
    for (int j = 0; j < 5; j++) o[j * n + i] = h16(f[j]);
}

// sum 4 K-piece slabs of GEMM1 (slice-major, 4 slabs per slice) -> fp16 C1
__global__ void reduce4_kernel(const float* __restrict__ P,
                               unsigned short* __restrict__ o) {
    size_t i0 = ((size_t)blockIdx.x * blockDim.x + threadIdx.x) * 4;
    size_t slice = i0 / NX;
    size_t r = i0 - slice * NX;
    const float* base = P + 4 * slice * NX + r;
    float4 s = *reinterpret_cast<const float4*>(base);
#pragma unroll
    for (int q = 1; q < 4; q++) {
        float4 v = *reinterpret_cast<const float4*>(base + q * NX);
        s.x += v.x; s.y += v.y; s.z += v.z; s.w += v.w;
    }
    *reinterpret_cast<uint2*>(o + i0) =
        make_uint2((uint32_t)h16(s.x) | ((uint32_t)h16(s.y) << 16),
                   (uint32_t)h16(s.z) | ((uint32_t)h16(s.w) << 16));
}

// inverse cos transform; folds GEMM2's 2-way split-K reduction
__global__ void inv_kernel(const float* __restrict__ P2,
                           float* __restrict__ out, int n) {
    int i = blockIdx.x * blockDim.x + threadIdx.x;
    if (i >= n) return;
    float g[5];
#pragma unroll
    for (int j = 0; j < 5; j++)
        g[j] = P2[(size_t)(2 * j) * NX + i] + P2[(size_t)(2 * j + 1) * NX + i];
    float d13 = 2.0f * RSQ2 * (g[1] - g[3]);
    float o0 = 0.125f * (g[0] + 2.0f * (g[1] + g[2] + g[3]) + g[4]);
    float o1 = 0.125f * ((g[0] - g[4]) + d13);
    float o2 = 0.125f * ((g[0] + g[4]) - 2.0f * g[2]);
    float o3 = 0.125f * ((g[0] - g[4]) - d13);
    float o4 = 0.125f * (g[0] - 2.0f * (g[1] - g[2] + g[3]) + g[4]);
    reinterpret_cast<float4*>(out)[(size_t)2 * i]     = make_float4(o0, o1, o2, o3);
    reinterpret_cast<float4*>(out)[(size_t)2 * i + 1] = make_float4(o4, o3, o2, o1);
}

// ---------------- fused heterogeneous GEMM + transform ----------------------
// Flat 1D grid. If mixed: groups of 21 CTAs = 5 GEMM + 16 transform (interleaved
// so both roles co-schedule). GEMM CTAs run the proven R9 inner loop on K-chunks
// [kBase, kBase+parts*cpp) split 'parts' ways; transform CTAs produce the NEXT
// K-piece of Af (disjoint columns -> no race).
#define BM 128
#define BN 128
#define ASTG (BM * 128)
#define BSTG (BN * 128)
#define STGB (ASTG + BSTG)
#define STAGES 3
#define GSMEM (STAGES * STGB)

__device__ __forceinline__ uint32_t swz(int row, int cbyte) {
    return (uint32_t)(row * 128 + (cbyte ^ ((row & 7) << 4)));
}

__global__ __launch_bounds__(256) void gemm_fused(
    const unsigned short* __restrict__ A, int lda, size_t sA,
    const unsigned short* __restrict__ B, int ldb, size_t sB,
    float* __restrict__ outP,
    int parts, int cpp, int kBase, int slabBase, int slabStride,
    int mixed, const float* __restrict__ tin,
    unsigned short* __restrict__ tout, int tKlo)
{
    const int tid = threadIdx.x;
    int idx;
    if (mixed) {
        int g = blockIdx.x / 21;
        int r = blockIdx.x - g * 21;
        if (r >= 5) {   // transform role
            transform_piece(tin, tout, tKlo, g * 16 + (r - 5), tid);
            return;
        }
        idx = g * 5 + r;
    } else {
        idx = blockIdx.x;
    }

    extern __shared__ char smem[];
    const uint32_t sbase = smem_u32(smem);
    const int wid = tid >> 5;
    const int lane = tid & 31;

    const int part = idx % parts;
    int rest = idx / parts;
    const int slice = rest % 5;
    const int t = rest / 5;             // 0..31
    const int n0 = (t >> 4) * 128;
    const int m0 = (t & 15) * 128;
    const int ktBegin = kBase + part * cpp;
    const int ktEnd = ktBegin + cpp;

    A += slice * sA;
    B += slice * sB;
    outP += (size_t)(slice * slabStride + slabBase + part) * NX;

    const int lrow = tid >> 3;          // 0..31
    const int lc16 = (tid & 7) << 4;    // byte col 0..112
    auto load_stage = [&](int s, int ktl) {
        int kk = ktl * 64;
        uint32_t ab = sbase + s * STGB;
        uint32_t bb = ab + ASTG;
#pragma unroll
        for (int tq = 0; tq < 4; tq++) {
            int row = lrow + tq * 32;
            cp16(ab + swz(row, lc16), A + (size_t)(m0 + row) * lda + kk + (lc16 >> 1));
        }
#pragma unroll
        for (int tq = 0; tq < 4; tq++) {
            int row = lrow + tq * 32;
            cp16(bb + swz(row, lc16), B + (size_t)(n0 + row) * ldb + kk + (lc16 >> 1));
        }
        asm volatile("cp.async.commit_group;" ::: "memory");
    };

    // warp tiling: 2 (M) x 4 (N) warps, warp tile 64x32
    const int wm = (wid >> 2) * 64;
    const int wn = (wid & 3) * 32;

    float d[4][4][4];
#pragma unroll
    for (int i = 0; i < 4; i++)
#pragma unroll
        for (int j = 0; j < 4; j++)
#pragma unroll
            for (int r = 0; r < 4; r++) d[i][j][r] = 0.0f;

    const int aRow = wm + (lane & 7) + ((lane >> 3) & 1) * 8;   // + f*16
    const int aC16 = ((lane >> 4) & 1) * 16;                     // + s*32
    const int bRow = wn + (lane & 7) + ((lane >> 4) & 1) * 8;   // + p*16
    const int bC16 = ((lane >> 3) & 1) * 16;                     // + s*32

    load_stage(0, ktBegin);
    if (ktBegin + 1 < ktEnd) load_stage(1, ktBegin + 1);

    for (int kt = ktBegin; kt < ktEnd; ++kt) {
        if (kt + 1 < ktEnd) asm volatile("cp.async.wait_group 1;" ::: "memory");
        else                asm volatile("cp.async.wait_group 0;" ::: "memory");
        __syncthreads();
        if (kt + 2 < ktEnd) load_stage((kt + 2 - ktBegin) % STAGES, kt + 2);

        uint32_t ab = sbase + ((kt - ktBegin) % STAGES) * STGB;
        uint32_t bb = ab + ASTG;

#pragma unroll
        for (int s = 0; s < 4; s++) {
            uint32_t a[4][4];
#pragma unroll
            for (int f = 0; f < 4; f++) {
                int row = aRow + f * 16;
                ldsm4(a[f][0], a[f][1], a[f][2], a[f][3],
                      ab + swz(row, s * 32 + aC16));
            }
            uint32_t b[2][4];
#pragma unroll
            for (int p = 0; p < 2; p++) {
                int row = bRow + p * 16;
                ldsm4(b[p][0], b[p][1], b[p][2], b[p][3],
                      bb + swz(row, s * 32 + bC16));
            }
#pragma unroll
            for (int mf = 0; mf < 4; mf++)
#pragma unroll
                for (int nf = 0; nf < 4; nf++) {
                    int p = nf >> 1, h = nf & 1;
                    mma16816(d[mf][nf], a[mf], b[p][h * 2], b[p][h * 2 + 1]);
                }
        }
    }

    const int q = lane >> 2;
    const int cp2 = (lane & 3) * 2;
#pragma unroll
    for (int mf = 0; mf < 4; mf++) {
#pragma unroll
        for (int nf = 0; nf < 4; nf++) {
            int row = m0 + wm + mf * 16 + q;
            int col = n0 + wn + nf * 8 + cp2;
#pragma unroll
            for (int half = 0; half < 2; half++) {
                size_t off = (size_t)(row + half * 8) * HH + col;
                *reinterpret_cast<float2*>(outP + off) =
                    make_float2(d[mf][nf][half * 2], d[mf][nf][half * 2 + 1]);
            }
        }
    }
}

extern "C" void kernel_launch(void* const* d_in, const int* in_sizes, int n_in,
                              void* d_out, int out_size) {
    const float* X = nullptr; const float* A = nullptr; const float* W = nullptr;
    for (int i = 0; i < n_in; i++) {
        if (in_sizes[i] == NN * NN * 8)      A = (const float*)d_in[i];
        else if (in_sizes[i] == NN * HH * 8) X = (const float*)d_in[i];
        else if (in_sizes[i] == HH * HH * 8) W = (const float*)d_in[i];
    }
    float* out = (float*)d_out;

    unsigned short *pAf, *pXf, *pWf, *pC1;
    float *pP1, *pP2;
    cudaGetSymbolAddress((void**)&pAf, g_Af);
    cudaGetSymbolAddress((void**)&pXf, g_Xf);
    cudaGetSymbolAddress((void**)&pWf, g_Wf);
    cudaGetSymbolAddress((void**)&pC1, g_C1);
    cudaGetSymbolAddress((void**)&pP1, g_P1);
    cudaGetSymbolAddress((void**)&pP2, g_P2);

    cudaFuncSetAttribute(gemm_fused,
                         cudaFuncAttributeMaxDynamicSharedMemorySize, GSMEM);

    // prelude: B-matrix transforms + A K-piece 0
    fwd_T_kernel<<<(int)((NX + 255) / 256), 256>>>(X, pXf, NN, HH);
    fwd_T_kernel<<<(int)((NW + 255) / 256), 256>>>(W, pWf, HH, HH);
    fwd_A0_kernel<<<512, 256>>>(A, pAf);

    // GEMM1 pipelined over 4 K-pieces (8 chunks each); launches 0-2 also
    // transform the NEXT piece via interleaved transform CTAs.
    for (int qp = 0; qp < 4; qp++) {
        int mixed = (qp < 3) ? 1 : 0;
        int grid = mixed ? 672 : 160;   // 160 GEMM + 512 transform
        gemm_fused<<<grid, 256, GSMEM>>>(
            pAf, NN, NA, pXf, NN, NX, pP1,
            /*parts*/1, /*cpp*/8, /*kBase*/qp * 8, /*slabBase*/qp, /*slabStride*/4,
            mixed, A, pAf, /*tKlo*/(qp + 1) * 512);
    }

    // reduce GEMM1 piece slabs -> C1 fp16
    reduce4_kernel<<<(int)(NJ * NX / 4 / 256), 256>>>(pP1, pC1);

    // GEMM2: K = 256 -> 4 chunks, split-K2; 320 CTAs, no transform
    gemm_fused<<<320, 256, GSMEM>>>(
        pC1, HH, NX, pWf, HH, NW, pP2,
        /*parts*/2, /*cpp*/2, /*kBase*/0, /*slabBase*/0, /*slabStride*/2,
        0, nullptr, nullptr, 0);

    // inverse transform (folds GEMM2 partial reduction)
    inv_kernel<<<(int)((NX + 255) / 256), 256>>>(pP2, out, (int)NX);
}

// round 15
// speedup vs baseline: 1.0491x; 1.0491x over previous
#include <cuda_runtime.h>
#include <cuda_fp16.h>
#include <cstdint>

#define NN 2048
#define HH 256
#define NJ 5
#define RSQ2 0.70710678118654752440f

#define NA ((size_t)NN * NN)
#define NX ((size_t)NN * HH)
#define NW ((size_t)HH * HH)

#define NTR 136   // transform-role CTAs (bids 0..135)

// fp16 operands stored as ushort
__device__ unsigned short g_Af[NJ * NA];      // 41.9 MB  [j][node][k]
__device__ unsigned short g_Xf[NJ * NX];      //  5.2 MB  [j][hidden][node]
__device__ unsigned short g_Wf[NJ * NW];      //  0.65 MB [j][h_out][h_in]
__device__ unsigned short g_C1[NJ * NX];      //  5.2 MB  [j][node][h]
__device__ float          g_P1[4 * NJ * NX];  // 42 MB: GEMM1 split-K4 partials
__device__ float          g_P2[2 * NJ * NX];  // 21 MB: GEMM2 split-K2 partials
__device__ int            g_done[4];          // stage completion counters

__device__ __forceinline__ uint32_t smem_u32(const void* p) {
    uint32_t a;
    asm("{ .reg .u64 t; cvta.to.shared.u64 t, %1; cvt.u32.u64 %0, t; }"
        : "=r"(a) : "l"(p));
    return a;
}
__device__ __forceinline__ void cp16(uint32_t dst, const void* src) {
    asm volatile("cp.async.cg.shared.global [%0], [%1], 16;" :: "r"(dst), "l"(src));
}
__device__ __forceinline__ void ldsm4(uint32_t& r0, uint32_t& r1, uint32_t& r2,
                                      uint32_t& r3, uint32_t addr) {
    asm volatile("ldmatrix.sync.aligned.m8n8.x4.shared.b16 {%0,%1,%2,%3}, [%4];"
                 : "=r"(r0), "=r"(r1), "=r"(r2), "=r"(r3) : "r"(addr));
}
__device__ __forceinline__ void mma16816(float* d, const uint32_t* a,
                                         uint32_t b0, uint32_t b1) {
    asm volatile(
        "mma.sync.aligned.m16n8k16.row.col.f32.f16.f16.f32 "
        "{%0,%1,%2,%3}, {%4,%5,%6,%7}, {%8,%9}, {%0,%1,%2,%3};"
        : "+f"(d[0]), "+f"(d[1]), "+f"(d[2]), "+f"(d[3])
        : "r"(a[0]), "r"(a[1]), "r"(a[2]), "r"(a[3]), "r"(b0), "r"(b1));
}

__device__ __forceinline__ void cos5(float4 lo, float4 hi, float f[5]) {
    float s04 = lo.x + hi.x, d04 = lo.x - hi.x;
    float s26 = lo.z + hi.z;
    float s15 = lo.y + hi.y, d15 = lo.y - hi.y;
    float s37 = lo.w + hi.w, d37 = lo.w - hi.w;
    float t = RSQ2 * (d15 - d37);
    f[0] = (s04 + s26) + (s15 + s37);
    f[1] = d04 + t;
    f[2] = s04 - s26;
    f[3] = d04 - t;
    f[4] = (s04 + s26) - (s15 + s37);
}
__device__ __forceinline__ unsigned short h16(float f) {
    __half h = __float2half_rn(f);
    return *reinterpret_cast<unsigned short*>(&h);
}

// one 2048-element unit of the A transform at K-piece offset kLo
__device__ __forceinline__ void transform_piece(const float* __restrict__ in,
                                                unsigned short* __restrict__ o,
                                                int kLo, int tIdx, int tid) {
    int tt = tIdx * 256 + tid;
    int row = tt >> 6;
    int col = kLo + ((tt & 63) << 3);
    size_t i0 = (size_t)row * NN + col;
    const float4* p = reinterpret_cast<const float4*>(in) + 2 * i0;
    unsigned short h[8][5];
#pragma unroll
    for (int e = 0; e < 8; e++) {
        float f[5]; cos5(p[2 * e], p[2 * e + 1], f);
#pragma unroll
        for (int j = 0; j < 5; j++) h[e][j] = h16(f[j]);
    }
#pragma unroll
    for (int j = 0; j < 5; j++) {
        *reinterpret_cast<uint4*>(o + j * NA + i0) =
            make_uint4((uint32_t)h[0][j] | ((uint32_t)h[1][j] << 16),
                       (uint32_t)h[2][j] | ((uint32_t)h[3][j] << 16),
                       (uint32_t)h[4][j] | ((uint32_t)h[5][j] << 16),
                       (uint32_t)h[6][j] | ((uint32_t)h[7][j] << 16));
    }
}

// one 2048-element unit of the transpose+cos transform (X or W)
__device__ __forceinline__ void fwd_T_unit(const float* __restrict__ in,
                                           unsigned short* __restrict__ o,
                                           int R, int C, int base, int tid) {
    size_t n = (size_t)R * C;
    for (int i = base + tid; i < base + 2048; i += 256) {
        int c = i / R, r = i - c * R;
        const float4* p = reinterpret_cast<const float4*>(in) + 2 * ((size_t)r * C + c);
        float f[5]; cos5(p[0], p[1], f);
#pragma unroll
        for (int j = 0; j < 5; j++) o[j * n + i] = h16(f[j]);
    }
}

__global__ void init_kernel() {
    if (threadIdx.x < 4) g_done[threadIdx.x] = 0;
}

// sum 4 split-K partials of GEMM1 -> fp16 C1
__global__ void reduce4_kernel(const float* __restrict__ P,
                               unsigned short* __restrict__ o) {
    size_t i0 = ((size_t)blockIdx.x * blockDim.x + threadIdx.x) * 4;
    size_t slice = i0 / NX;
    size_t r = i0 - slice * NX;
    const float* base = P + 4 * slice * NX + r;
    float4 s = *reinterpret_cast<const float4*>(base);
#pragma unroll
    for (int q = 1; q < 4; q++) {
        float4 v = *reinterpret_cast<const float4*>(base + q * NX);
        s.x += v.x; s.y += v.y; s.z += v.z; s.w += v.w;
    }
    *reinterpret_cast<uint2*>(o + i0) =
        make_uint2((uint32_t)h16(s.x) | ((uint32_t)h16(s.y) << 16),
                   (uint32_t)h16(s.z) | ((uint32_t)h16(s.w) << 16));
}

// inverse cos transform; folds GEMM2's 2-way split-K reduction
__global__ void inv_kernel(const float* __restrict__ P2,
                           float* __restrict__ out, int n) {
    int i = blockIdx.x * blockDim.x + threadIdx.x;
    if (i >= n) return;
    float g[5];
#pragma unroll
    for (int j = 0; j < 5; j++)
        g[j] = P2[(size_t)(2 * j) * NX + i] + P2[(size_t)(2 * j + 1) * NX + i];
    float d13 = 2.0f * RSQ2 * (g[1] - g[3]);
    float o0 = 0.125f * (g[0] + 2.0f * (g[1] + g[2] + g[3]) + g[4]);
    float o1 = 0.125f * ((g[0] - g[4]) + d13);
    float o2 = 0.125f * ((g[0] + g[4]) - 2.0f * g[2]);
    float o3 = 0.125f * ((g[0] - g[4]) - d13);
    float o4 = 0.125f * (g[0] - 2.0f * (g[1] - g[2] + g[3]) + g[4]);
    reinterpret_cast<float4*>(out)[(size_t)2 * i]     = make_float4(o0, o1, o2, o3);
    reinterpret_cast<float4*>(out)[(size_t)2 * i + 1] = make_float4(o4, o3, o2, o1);
}

#define BM 128
#define BN 128
#define ASTG (BM * 128)
#define BSTG (BN * 128)
#define STGB (ASTG + BSTG)
#define STAGES 3
#define GSMEM (STAGES * STGB)

__device__ __forceinline__ uint32_t swz(int row, int cbyte) {
    return (uint32_t)(row * 128 + (cbyte ^ (((uint32_t)(row & 7)) << 4)));
}

// ---------------- mega kernel: transform producers + GEMM1 consumers --------
// bids 0..135: transform role. Stage 0 = Xf + Wf + A piece 0 (800 units);
// stages 1..3 = A pieces 1..3 (512 units each). Arrive on g_done[s].
// bids 136..775: GEMM role, part-major: idx = (bid-136); part = idx/160;
// within part: slice = (idx%160)/32, tile = (idx%160)%32. Waits g_done[part].
__global__ __launch_bounds__(256, 2) void mega_kernel(
    const float* __restrict__ Araw, const float* __restrict__ Xraw,
    const float* __restrict__ Wraw,
    unsigned short* __restrict__ Af, unsigned short* __restrict__ Xf,
    unsigned short* __restrict__ Wf, float* __restrict__ P1)
{
    const int tid = threadIdx.x;

    if (blockIdx.x < NTR) {
        const int c = blockIdx.x;
        for (int s = 0; s < 4; s++) {
            int total = (s == 0) ? 800 : 512;
            for (int u = c; u < total; u += NTR) {
                if (s == 0) {
                    if (u < 256)       fwd_T_unit(Xraw, Xf, NN, HH, u * 2048, tid);
                    else if (u < 288)  fwd_T_unit(Wraw, Wf, HH, HH, (u - 256) * 2048, tid);
                    else               transform_piece(Araw, Af, 0, u - 288, tid);
                } else {
                    transform_piece(Araw, Af, s * 512, u, tid);
                }
            }
            __threadfence();
            __syncthreads();
            if (tid == 0) atomicAdd(&g_done[s], 1);
        }
        return;
    }

    // ---- GEMM1 role (R9 inner loop) ----
    extern __shared__ char smem[];
    const uint32_t sbase = smem_u32(smem);
    const int wid = tid >> 5;
    const int lane = tid & 31;

    int idx = blockIdx.x - NTR;         // 0..639
    const int part = idx / 160;
    int r = idx - part * 160;
    const int slice = r / 32;
    const int t = r - slice * 32;
    const int n0 = (t >> 4) * 128;
    const int m0 = (t & 15) * 128;
    const int ktBegin = part * 8;
    const int ktEnd = ktBegin + 8;

    // gate: this part's K-piece (and transitively all earlier stages incl. Xf)
    if (tid == 0) {
        while (atomicAdd(&g_done[part], 0) < NTR) __nanosleep(1024);
    }
    __syncthreads();

    const unsigned short* A = Af + slice * NA;
    const unsigned short* B = Xf + slice * NX;
    float* outP = P1 + (size_t)(slice * 4 + part) * NX;

    const int lrow = tid >> 3;
    const int lc16 = (tid & 7) << 4;
    auto load_stage = [&](int s, int ktl) {
        int kk = ktl * 64;
        uint32_t ab = sbase + s * STGB;
        uint32_t bb = ab + ASTG;
#pragma unroll
        for (int tq = 0; tq < 4; tq++) {
            int row = lrow + tq * 32;
            cp16(ab + swz(row, lc16), A + (size_t)(m0 + row) * NN + kk + (lc16 >> 1));
        }
#pragma unroll
        for (int tq = 0; tq < 4; tq++) {
            int row = lrow + tq * 32;
            cp16(bb + swz(row, lc16), B + (size_t)(n0 + row) * NN + kk + (lc16 >> 1));
        }
        asm volatile("cp.async.commit_group;" ::: "memory");
    };

    const int wm = (wid >> 2) * 64;
    const int wn = (wid & 3) * 32;

    float d[4][4][4];
#pragma unroll
    for (int i = 0; i < 4; i++)
#pragma unroll
        for (int j = 0; j < 4; j++)
#pragma unroll
            for (int rr = 0; rr < 4; rr++) d[i][j][rr] = 0.0f;

    const int aRow = wm + (lane & 7) + ((lane >> 3) & 1) * 8;
    const int aC16 = ((lane >> 4) & 1) * 16;
    const int bRow = wn + (lane & 7) + ((lane >> 4) & 1) * 8;
    const int bC16 = ((lane >> 3) & 1) * 16;

    load_stage(0, ktBegin);
    load_stage(1, ktBegin + 1);

    for (int kt = ktBegin; kt < ktEnd; ++kt) {
        if (kt + 1 < ktEnd) asm volatile("cp.async.wait_group 1;" ::: "memory");
        else                asm volatile("cp.async.wait_group 0;" ::: "memory");
        __syncthreads();
        if (kt + 2 < ktEnd) load_stage((kt + 2 - ktBegin) % STAGES, kt + 2);

        uint32_t ab = sbase + ((kt - ktBegin) % STAGES) * STGB;
        uint32_t bb = ab + ASTG;

#pragma unroll
        for (int s = 0; s < 4; s++) {
            uint32_t a[4][4];
#pragma unroll
            for (int f = 0; f < 4; f++) {
                int row = aRow + f * 16;
                ldsm4(a[f][0], a[f][1], a[f][2], a[f][3],
                      ab + swz(row, s * 32 + aC16));
            }
            uint32_t b[2][4];
#pragma unroll
            for (int p = 0; p < 2; p++) {
                int row = bRow + p * 16;
                ldsm4(b[p][0], b[p][1], b[p][2], b[p][3],
                      bb + swz(row, s * 32 + bC16));
            }
#pragma unroll
            for (int mf = 0; mf < 4; mf++)
#pragma unroll
                for (int nf = 0; nf < 4; nf++) {
                    int p = nf >> 1, h = nf & 1;
                    mma16816(d[mf][nf], a[mf], b[p][h * 2], b[p][h * 2 + 1]);
                }
        }
    }

    const int q = lane >> 2;
    const int cp2 = (lane & 3) * 2;
#pragma unroll
    for (int mf = 0; mf < 4; mf++) {
#pragma unroll
        for (int nf = 0; nf < 4; nf++) {
            int row = m0 + wm + mf * 16 + q;
            int col = n0 + wn + nf * 8 + cp2;
#pragma unroll
            for (int half = 0; half < 2; half++) {
                size_t off = (size_t)(row + half * 8) * HH + col;
                *reinterpret_cast<float2*>(outP + off) =
                    make_float2(d[mf][nf][half * 2], d[mf][nf][half * 2 + 1]);
            }
        }
    }
}

// ---------------- plain fp16 GEMM with split-K (for GEMM2, proven R9) -------
__global__ __launch_bounds__(256) void gemm_kernel(
    const unsigned short* __restrict__ A, int lda, size_t sA,
    const unsigned short* __restrict__ B, int ldb, size_t sB,
    float* __restrict__ outP, int nPer, int splitCnt, int kTot)
{
    extern __shared__ char smem[];
    const uint32_t sbase = smem_u32(smem);
    const int tid = threadIdx.x;
    const int wid = tid >> 5;
    const int lane = tid & 31;
    const int z = blockIdx.z;
    const int slice = z / splitCnt;
    const int part = z - slice * splitCnt;
    const int ktBegin = part * nPer;
    const int ktEnd = min(ktBegin + nPer, kTot);
    const int m0 = blockIdx.x * BM;
    const int n0 = blockIdx.y * BN;

    A += slice * sA;
    B += slice * sB;
    outP += (size_t)z * NX;

    const int lrow = tid >> 3;
    const int lc16 = (tid & 7) << 4;
    auto load_stage = [&](int s, int ktl) {
        int kk = ktl * 64;
        uint32_t ab = sbase + s * STGB;
        uint32_t bb = ab + ASTG;
#pragma unroll
        for (int tq = 0; tq < 4; tq++) {
            int row = lrow + tq * 32;
            cp16(ab + swz(row, lc16), A + (size_t)(m0 + row) * lda + kk + (lc16 >> 1));
        }
#pragma unroll
        for (int tq = 0; tq < 4; tq++) {
            int row = lrow + tq * 32;
            cp16(bb + swz(row, lc16), B + (size_t)(n0 + row) * ldb + kk + (lc16 >> 1));
        }
        asm volatile("cp.async.commit_group;" ::: "memory");
    };

    const int wm = (wid >> 2) * 64;
    const int wn = (wid & 3) * 32;

    float d[4][4][4];
#pragma unroll
    for (int i = 0; i < 4; i++)
#pragma unroll
        for (int j = 0; j < 4; j++)
#pragma unroll
            for (int rr = 0; rr < 4; rr++) d[i][j][rr] = 0.0f;

    const int aRow = wm + (lane & 7) + ((lane >> 3) & 1) * 8;
    const int aC16 = ((lane >> 4) & 1) * 16;
    const int bRow = wn + (lane & 7) + ((lane >> 4) & 1) * 8;
    const int bC16 = ((lane >> 3) & 1) * 16;

    load_stage(0, ktBegin);
    if (ktBegin + 1 < ktEnd) load_stage(1, ktBegin + 1);

    for (int kt = ktBegin; kt < ktEnd; ++kt) {
        if (kt + 1 < ktEnd) asm volatile("cp.async.wait_group 1;" ::: "memory");
        else                asm volatile("cp.async.wait_group 0;" ::: "memory");
        __syncthreads();
        if (kt + 2 < ktEnd) load_stage((kt + 2 - ktBegin) % STAGES, kt + 2);

        uint32_t ab = sbase + ((kt - ktBegin) % STAGES) * STGB;
        uint32_t bb = ab + ASTG;

#pragma unroll
        for (int s = 0; s < 4; s++) {
            uint32_t a[4][4];
#pragma unroll
            for (int f = 0; f < 4; f++) {
                int row = aRow + f * 16;
                ldsm4(a[f][0], a[f][1], a[f][2], a[f][3],
                      ab + swz(row, s * 32 + aC16));
            }
            uint32_t b[2][4];
#pragma unroll
            for (int p = 0; p < 2; p++) {
                int row = bRow + p * 16;
                ldsm4(b[p][0], b[p][1], b[p][2], b[p][3],
                      bb + swz(row, s * 32 + bC16));
            }
#pragma unroll
            for (int mf = 0; mf < 4; mf++)
#pragma unroll
                for (int nf = 0; nf < 4; nf++) {
                    int p = nf >> 1, h = nf & 1;
                    mma16816(d[mf][nf], a[mf], b[p][h * 2], b[p][h * 2 + 1]);
                }
        }
    }

    const int q = lane >> 2;
    const int cp2 = (lane & 3) * 2;
#pragma unroll
    for (int mf = 0; mf < 4; mf++) {
#pragma unroll
        for (int nf = 0; nf < 4; nf++) {
            int row = m0 + wm + mf * 16 + q;
            int col = n0 + wn + nf * 8 + cp2;
#pragma unroll
            for (int half = 0; half < 2; half++) {
                size_t off = (size_t)(row + half * 8) * HH + col;
                *reinterpret_cast<float2*>(outP + off) =
                    make_float2(d[mf][nf][half * 2], d[mf][nf][half * 2 + 1]);
            }
        }
    }
}

extern "C" void kernel_launch(void* const* d_in, const int* in_sizes, int n_in,
                              void* d_out, int out_size) {
    const float* X = nullptr; const float* A = nullptr; const float* W = nullptr;
    for (int i = 0; i < n_in; i++) {
        if (in_sizes[i] == NN * NN * 8)      A = (const float*)d_in[i];
        else if (in_sizes[i] == NN * HH * 8) X = (const float*)d_in[i];
        else if (in_sizes[i] == HH * HH * 8) W = (const float*)d_in[i];
    }
    float* out = (float*)d_out;

    unsigned short *pAf, *pXf, *pWf, *pC1;
    float *pP1, *pP2;
    cudaGetSymbolAddress((void**)&pAf, g_Af);
    cudaGetSymbolAddress((void**)&pXf, g_Xf);
    cudaGetSymbolAddress((void**)&pWf, g_Wf);
    cudaGetSymbolAddress((void**)&pC1, g_C1);
    cudaGetSymbolAddress((void**)&pP1, g_P1);
    cudaGetSymbolAddress((void**)&pP2, g_P2);

    cudaFuncSetAttribute(mega_kernel,
                         cudaFuncAttributeMaxDynamicSharedMemorySize, GSMEM);
    cudaFuncSetAttribute(gemm_kernel,
                         cudaFuncAttributeMaxDynamicSharedMemorySize, GSMEM);

    // reset stage counters (graph-replay safe, stream-ordered)
    init_kernel<<<1, 32>>>();

    // fused transforms + GEMM1 (split-K4, piece-gated)
    mega_kernel<<<NTR + 640, 256, GSMEM>>>(A, X, W, pAf, pXf, pWf, pP1);

    // reduce GEMM1 partials -> C1 fp16
    reduce4_kernel<<<(int)(NJ * NX / 4 / 256), 256>>>(pP1, pC1);

    // GEMM2: K = 256 -> 4 chunks, split-K2; grid (16,2,10)
    gemm_kernel<<<dim3(16, 2, 2 * NJ), 256, GSMEM>>>(
        pC1, HH, NX, pWf, HH, NW, pP2, 2, 2, 4);

    // inverse transform (folds GEMM2 partial reduction)
    inv_kernel<<<(int)((NX + 255) / 256), 256>>>(pP2, out, (int)NX);
}